// round 5
// baseline (speedup 1.0000x reference)
#include <cuda_runtime.h>
#include <cfloat>
#include <climits>
#include <math.h>

#define NPTS     4096
#define G_TOTAL  65536
#define NBUCK    64
#define INV_CELL (1.0f / 16.0f)
#define NEG_INF_F (__int_as_float(0xff800000))

#define BLOCK_T  1024   // threads per block (phase A parallelism)
#define GPTS     256    // grid points per block (phase B threads)
#define CAPB     12     // per-bucket capacity
#define OCAP     32     // overflow list capacity
#define PAD      0.25f  // window padding covering reference d2 rounding slack

// Monotonic float<->int key mapping (handles negatives)
__device__ __forceinline__ int f2ord(float f) {
    int i = __float_as_int(f);
    return (i >= 0) ? i : (i ^ 0x7fffffff);
}
__device__ __forceinline__ float ord2f(int i) {
    return __int_as_float((i >= 0) ? i : (i ^ 0x7fffffff));
}

// Lexicographic (d, pid) top-4 insertion — exactly matches top_k tie-breaking.
__device__ __forceinline__ void insert4(
    float d, int pid, float sc,
    float& da, float& db, float& dc, float& dd,
    int& ia, int& ib, int& ic, int& id_,
    float& sa, float& sb, float& sc_, float& sd)
{
    if (d < dd || (d == dd && pid < id_)) {
        dd = d; id_ = pid; sd = sc;
        if (dd < dc || (dd == dc && id_ < ic)) {
            float td = dc; int ti = ic; float ts = sc_;
            dc = dd; ic = id_; sc_ = sd;
            dd = td; id_ = ti; sd = ts;
            if (dc < db || (dc == db && ic < ib)) {
                td = db; ti = ib; ts = sb;
                db = dc; ib = ic; sb = sc_;
                dc = td; ic = ti; sc_ = ts;
                if (db < da || (db == da && ib < ia)) {
                    td = da; ti = ia; ts = sa;
                    da = db; ia = ib; sa = sb;
                    db = td; ib = ti; sb = ts;
                }
            }
        }
    }
}

// ---------------------------------------------------------------------------
// Single fused kernel. One block per 256 grid points (one grid row), 1024
// threads. Phase A: all 1024 threads scan the 4096 points (4 coalesced float4
// loads each) and bin the block's y-strip survivors into smem x-buckets.
// Phase B: threads 0..255 each finish one grid point.
// ---------------------------------------------------------------------------
__global__ __launch_bounds__(BLOCK_T) void pump_fused_kernel(
    const float4* __restrict__ pos,      // (NPTS, 4)
    const float*  __restrict__ scores,   // (NPTS,)
    const float2* __restrict__ grid,     // (G, 2)
    const float*  __restrict__ accu,     // (G, 6)
    const float*  __restrict__ scale_p,
    const float*  __restrict__ code_p,
    float*        __restrict__ out)      // (G, 6)
{
    __shared__ float4 s_buck[NBUCK * CAPB];
    __shared__ int    s_bpid[NBUCK * CAPB];
    __shared__ int    s_cnt[NBUCK];
    __shared__ float4 s_ovf[OCAP];
    __shared__ int    s_opid[OCAP];
    __shared__ int    s_ocnt, s_fb, s_ymin, s_ymax;

    const int tid = threadIdx.x;
    const int lane = tid & 31;
    const bool is_g = (tid < GPTS);
    const int g = blockIdx.x * GPTS + (is_g ? tid : 0);

    const float scale = *scale_p;
    const float dist_max = __fsub_rn(__fmul_rn(8.0f, scale), 1e-7f);
    const float r = dist_max;
    const float rp = r + PAD;   // padded window radius

    // ---- init smem ----
    if (tid < NBUCK) s_cnt[tid] = 0;
    if (tid == 0) { s_ocnt = 0; s_fb = 0; s_ymin = INT_MAX; s_ymax = INT_MIN; }
    __syncthreads();

    // ---- grid point + block y-range (warp reduce, 8 atomics) ----
    float gx = 0.0f, gy = 0.0f, g2 = 0.0f;
    if (is_g) {
        const float2 gp = grid[g];
        gx = gp.x; gy = gp.y;
        g2 = __fadd_rn(__fmul_rn(gx, gx), __fmul_rn(gy, gy));
        int lo = f2ord(gy), hi = lo;
        #pragma unroll
        for (int o = 16; o > 0; o >>= 1) {
            lo = min(lo, __shfl_xor_sync(0xffffffffu, lo, o));
            hi = max(hi, __shfl_xor_sync(0xffffffffu, hi, o));
        }
        if (lane == 0) { atomicMin(&s_ymin, lo); atomicMax(&s_ymax, hi); }
    }
    __syncthreads();
    const float ylo = ord2f(s_ymin) - rp;
    const float yhi = ord2f(s_ymax) + rp;

    // ---- Phase A: scan all points, bin survivors into x-buckets ----
    #pragma unroll
    for (int i = 0; i < NPTS / BLOCK_T; i++) {
        const int idx = tid + i * BLOCK_T;
        const float4 p = pos[idx];
        if (p.y > ylo && p.y < yhi) {
            int bx = (int)floorf(p.x * INV_CELL);
            bx = min(NBUCK - 1, max(0, bx));
            const int slot = atomicAdd(&s_cnt[bx], 1);
            const float p2 = __fadd_rn(__fmul_rn(p.x, p.x), __fmul_rn(p.y, p.y));
            const float sc = scores[idx];
            const float4 e = make_float4(p.x, p.y, p2, sc);
            if (slot < CAPB) {
                s_buck[bx * CAPB + slot] = e;
                s_bpid[bx * CAPB + slot] = idx;
            } else {
                const int o = atomicAdd(&s_ocnt, 1);
                if (o < OCAP) { s_ovf[o] = e; s_opid[o] = idx; }
                else s_fb = 1;   // pathological input: full-scan fallback
            }
        }
    }
    __syncthreads();

    if (!is_g) return;

    // ---- issue accu loads early (overlap with compute) ----
    const float2* acc2 = (const float2*)accu;
    const float2 a01 = acc2[g * 3 + 0];
    const float2 a23 = acc2[g * 3 + 1];
    const float2 a45 = acc2[g * 3 + 2];

    // ---- Phase B: top-4 by (d, pid) over the padded x-window ----
    float da = FLT_MAX, db = FLT_MAX, dc = FLT_MAX, dd = FLT_MAX;
    int   ia = INT_MAX, ib = INT_MAX, ic = INT_MAX, id_ = INT_MAX;
    float sa = 0.0f,    sb = 0.0f,    sc_ = 0.0f,   sd = 0.0f;

    if (!s_fb) {
        int bx0 = (int)floorf((gx - rp) * INV_CELL);
        int bx1 = (int)floorf((gx + rp) * INV_CELL);
        bx0 = min(NBUCK - 1, max(0, bx0));
        bx1 = min(NBUCK - 1, max(0, bx1));

        for (int bx = bx0; bx <= bx1; bx++) {
            const int n = min(s_cnt[bx], CAPB);
            const int base = bx * CAPB;
            for (int k = 0; k < n; k++) {
                const float4 e = s_buck[base + k];
                const int pid = s_bpid[base + k];
                const float dot = __fmaf_rn(e.y, gy, __fmul_rn(e.x, gx));
                const float d2 = __fsub_rn(__fadd_rn(e.z, g2),
                                           __fmul_rn(2.0f, dot));
                const float d = sqrtf(fmaxf(d2, 1e-12f));
                insert4(d, pid, e.w, da, db, dc, dd, ia, ib, ic, id_,
                        sa, sb, sc_, sd);
            }
        }
        const int on = min(s_ocnt, OCAP);
        for (int k = 0; k < on; k++) {
            const float4 e = s_ovf[k];
            const int pid = s_opid[k];
            const float dot = __fmaf_rn(e.y, gy, __fmul_rn(e.x, gx));
            const float d2 = __fsub_rn(__fadd_rn(e.z, g2),
                                       __fmul_rn(2.0f, dot));
            const float d = sqrtf(fmaxf(d2, 1e-12f));
            insert4(d, pid, e.w, da, db, dc, dd, ia, ib, ic, id_,
                    sa, sb, sc_, sd);
        }
    } else {
        // Fallback: scan everything from gmem (correct for any input).
        for (int idx = 0; idx < NPTS; idx++) {
            const float4 p = pos[idx];
            const float p2 = __fadd_rn(__fmul_rn(p.x, p.x), __fmul_rn(p.y, p.y));
            const float scv = scores[idx];
            const float dot = __fmaf_rn(p.y, gy, __fmul_rn(p.x, gx));
            const float d2 = __fsub_rn(__fadd_rn(p2, g2),
                                       __fmul_rn(2.0f, dot));
            const float d = sqrtf(fmaxf(d2, 1e-12f));
            insert4(d, idx, scv, da, db, dc, dd, ia, ib, ic, id_,
                    sa, sb, sc_, sd);
        }
    }

    // ---- Finalize: filter (d <= 2*d0) & (d < dist_max); max score,
    //      first occurrence wins ties (strict >) ----
    const float thr = __fmul_rn(2.0f, da);   // exact (power of 2)

    float best = NEG_INF_F;
    int bestid = 0;
    if (da <= thr && da < dist_max && sa  > best) { best = sa;  bestid = ia; }
    if (db <= thr && db < dist_max && sb  > best) { best = sb;  bestid = ib; }
    if (dc <= thr && dc < dist_max && sc_ > best) { best = sc_; bestid = ic; }
    if (dd <= thr && dd < dist_max && sd  > best) { best = sd;  bestid = id_; }

    float2* out2 = (float2*)out;
    if (best > a45.x) {
        const float4 pr = pos[bestid];
        const float code = *code_p;
        out2[g * 3 + 0] = make_float2(pr.x, pr.y);
        out2[g * 3 + 1] = make_float2(pr.z, pr.w);
        out2[g * 3 + 2] = make_float2(best, code);
    } else {
        out2[g * 3 + 0] = a01;
        out2[g * 3 + 1] = a23;
        out2[g * 3 + 2] = a45;
    }
}

// ---------------------------------------------------------------------------
// Inputs (metadata order): pos (4096,4) f32, scores (4096,) f32,
// grid (65536,2) f32, accu (65536,6) f32, scale () f32, code () f32.
// ---------------------------------------------------------------------------
extern "C" void kernel_launch(void* const* d_in, const int* in_sizes, int n_in,
                              void* d_out, int out_size)
{
    const float4* pos    = (const float4*)d_in[0];
    const float*  scores = (const float*) d_in[1];
    const float2* grid   = (const float2*)d_in[2];
    const float*  accu   = (const float*) d_in[3];
    const float*  scale  = (const float*) d_in[4];
    const float*  code   = (const float*) d_in[5];
    float* out = (float*)d_out;

    pump_fused_kernel<<<G_TOTAL / GPTS, BLOCK_T>>>(pos, scores, grid, accu,
                                                   scale, code, out);
}

// round 6
// speedup vs baseline: 1.4048x; 1.4048x over previous
#include <cuda_runtime.h>
#include <cfloat>
#include <climits>
#include <math.h>

#define NPTS     4096
#define G_TOTAL  65536
#define NBUCK    64
#define INV_CELL (1.0f / 16.0f)
#define NEG_INF_F (__int_as_float(0xff800000))

#define BLOCK_T  1024   // threads per block
#define GPTS     512    // grid points per block (2 grid rows)
#define NBLK     (G_TOTAL / GPTS)   // 128 blocks -> single wave on 148 SMs
#define CAPB     16     // per-bucket capacity
#define OCAP     64     // overflow list capacity
#define PAD      0.25f  // window padding covering reference d2 rounding slack

// Monotonic float<->int key mapping (handles negatives)
__device__ __forceinline__ int f2ord(float f) {
    int i = __float_as_int(f);
    return (i >= 0) ? i : (i ^ 0x7fffffff);
}
__device__ __forceinline__ float ord2f(int i) {
    return __int_as_float((i >= 0) ? i : (i ^ 0x7fffffff));
}

// Lexicographic (d, pid) top-4 insertion — exactly matches top_k tie-breaking.
__device__ __forceinline__ void insert4(
    float d, int pid, float sc,
    float& da, float& db, float& dc, float& dd,
    int& ia, int& ib, int& ic, int& id_,
    float& sa, float& sb, float& sc_, float& sd)
{
    if (d < dd || (d == dd && pid < id_)) {
        dd = d; id_ = pid; sd = sc;
        if (dd < dc || (dd == dc && id_ < ic)) {
            float td = dc; int ti = ic; float ts = sc_;
            dc = dd; ic = id_; sc_ = sd;
            dd = td; id_ = ti; sd = ts;
            if (dc < db || (dc == db && ic < ib)) {
                td = db; ti = ib; ts = sb;
                db = dc; ib = ic; sb = sc_;
                dc = td; ic = ti; sc_ = ts;
                if (db < da || (db == da && ib < ia)) {
                    td = da; ti = ia; ts = sa;
                    da = db; ia = ib; sa = sb;
                    db = td; ib = ti; sb = ts;
                }
            }
        }
    }
}

// ---------------------------------------------------------------------------
// Single fused kernel, ONE wave: 128 blocks x 1024 threads.
// Each block owns 512 grid points (2 grid rows).
// Phase A: all 1024 threads scan the 4096 points (4 coalesced float4 loads)
//          and bin the block's y-strip survivors into smem x-buckets.
// Phase B: threads 0..511 each finish one grid point.
// ---------------------------------------------------------------------------
__global__ __launch_bounds__(BLOCK_T) void pump_fused_kernel(
    const float4* __restrict__ pos,      // (NPTS, 4)
    const float*  __restrict__ scores,   // (NPTS,)
    const float2* __restrict__ grid,     // (G, 2)
    const float*  __restrict__ accu,     // (G, 6)
    const float*  __restrict__ scale_p,
    const float*  __restrict__ code_p,
    float*        __restrict__ out)      // (G, 6)
{
    __shared__ float4 s_buck[NBUCK * CAPB];
    __shared__ int    s_bpid[NBUCK * CAPB];
    __shared__ int    s_cnt[NBUCK];
    __shared__ float4 s_ovf[OCAP];
    __shared__ int    s_opid[OCAP];
    __shared__ int    s_ocnt, s_fb, s_ymin, s_ymax;

    const int tid = threadIdx.x;
    const int lane = tid & 31;
    const bool is_g = (tid < GPTS);
    const int g = blockIdx.x * GPTS + (is_g ? tid : 0);

    const float scale = __ldg(scale_p);
    const float dist_max = __fsub_rn(__fmul_rn(8.0f, scale), 1e-7f);
    const float r = dist_max;
    const float rp = r + PAD;   // padded window radius

    // ---- init smem ----
    if (tid < NBUCK) s_cnt[tid] = 0;
    if (tid == 0) { s_ocnt = 0; s_fb = 0; s_ymin = INT_MAX; s_ymax = INT_MIN; }
    __syncthreads();

    // ---- grid point + block y-range (warp reduce, lane-0 atomics) ----
    float gx = 0.0f, gy = 0.0f, g2 = 0.0f;
    if (is_g) {
        const float2 gp = grid[g];
        gx = gp.x; gy = gp.y;
        g2 = __fadd_rn(__fmul_rn(gx, gx), __fmul_rn(gy, gy));
        int lo = f2ord(gy), hi = lo;
        #pragma unroll
        for (int o = 16; o > 0; o >>= 1) {
            lo = min(lo, __shfl_xor_sync(0xffffffffu, lo, o));
            hi = max(hi, __shfl_xor_sync(0xffffffffu, hi, o));
        }
        if (lane == 0) { atomicMin(&s_ymin, lo); atomicMax(&s_ymax, hi); }
    }
    __syncthreads();
    const float ylo = ord2f(s_ymin) - rp;
    const float yhi = ord2f(s_ymax) + rp;

    // ---- Phase A: scan all points, bin survivors into x-buckets ----
    #pragma unroll
    for (int i = 0; i < NPTS / BLOCK_T; i++) {
        const int idx = tid + i * BLOCK_T;
        const float4 p = pos[idx];
        if (p.y > ylo && p.y < yhi) {
            int bx = (int)floorf(p.x * INV_CELL);
            bx = min(NBUCK - 1, max(0, bx));
            const int slot = atomicAdd(&s_cnt[bx], 1);
            const float p2 = __fadd_rn(__fmul_rn(p.x, p.x), __fmul_rn(p.y, p.y));
            const float sc = scores[idx];
            const float4 e = make_float4(p.x, p.y, p2, sc);
            if (slot < CAPB) {
                s_buck[bx * CAPB + slot] = e;
                s_bpid[bx * CAPB + slot] = idx;
            } else {
                const int o = atomicAdd(&s_ocnt, 1);
                if (o < OCAP) { s_ovf[o] = e; s_opid[o] = idx; }
                else s_fb = 1;   // pathological input: full-scan fallback
            }
        }
    }
    __syncthreads();

    if (!is_g) return;

    // ---- issue accu loads early (overlap with compute) ----
    const float2* acc2 = (const float2*)accu;
    const float2 a01 = acc2[g * 3 + 0];
    const float2 a23 = acc2[g * 3 + 1];
    const float2 a45 = acc2[g * 3 + 2];

    // ---- Phase B: top-4 by (d, pid) over the padded x-window ----
    float da = FLT_MAX, db = FLT_MAX, dc = FLT_MAX, dd = FLT_MAX;
    int   ia = INT_MAX, ib = INT_MAX, ic = INT_MAX, id_ = INT_MAX;
    float sa = 0.0f,    sb = 0.0f,    sc_ = 0.0f,   sd = 0.0f;

    if (!s_fb) {
        int bx0 = (int)floorf((gx - rp) * INV_CELL);
        int bx1 = (int)floorf((gx + rp) * INV_CELL);
        bx0 = min(NBUCK - 1, max(0, bx0));
        bx1 = min(NBUCK - 1, max(0, bx1));

        for (int bx = bx0; bx <= bx1; bx++) {
            const int n = min(s_cnt[bx], CAPB);
            const int base = bx * CAPB;
            for (int k = 0; k < n; k++) {
                const float4 e = s_buck[base + k];
                const int pid = s_bpid[base + k];
                const float dot = __fmaf_rn(e.y, gy, __fmul_rn(e.x, gx));
                const float d2 = __fsub_rn(__fadd_rn(e.z, g2),
                                           __fmul_rn(2.0f, dot));
                const float d = sqrtf(fmaxf(d2, 1e-12f));
                insert4(d, pid, e.w, da, db, dc, dd, ia, ib, ic, id_,
                        sa, sb, sc_, sd);
            }
        }
        const int on = min(s_ocnt, OCAP);
        for (int k = 0; k < on; k++) {
            const float4 e = s_ovf[k];
            const int pid = s_opid[k];
            const float dot = __fmaf_rn(e.y, gy, __fmul_rn(e.x, gx));
            const float d2 = __fsub_rn(__fadd_rn(e.z, g2),
                                       __fmul_rn(2.0f, dot));
            const float d = sqrtf(fmaxf(d2, 1e-12f));
            insert4(d, pid, e.w, da, db, dc, dd, ia, ib, ic, id_,
                    sa, sb, sc_, sd);
        }
    } else {
        // Fallback: scan everything from gmem (correct for any input).
        for (int idx = 0; idx < NPTS; idx++) {
            const float4 p = pos[idx];
            const float p2 = __fadd_rn(__fmul_rn(p.x, p.x), __fmul_rn(p.y, p.y));
            const float scv = scores[idx];
            const float dot = __fmaf_rn(p.y, gy, __fmul_rn(p.x, gx));
            const float d2 = __fsub_rn(__fadd_rn(p2, g2),
                                       __fmul_rn(2.0f, dot));
            const float d = sqrtf(fmaxf(d2, 1e-12f));
            insert4(d, idx, scv, da, db, dc, dd, ia, ib, ic, id_,
                    sa, sb, sc_, sd);
        }
    }

    // ---- Finalize: filter (d <= 2*d0) & (d < dist_max); max score,
    //      first occurrence wins ties (strict >) ----
    const float thr = __fmul_rn(2.0f, da);   // exact (power of 2)

    float best = NEG_INF_F;
    int bestid = 0;
    if (da <= thr && da < dist_max && sa  > best) { best = sa;  bestid = ia; }
    if (db <= thr && db < dist_max && sb  > best) { best = sb;  bestid = ib; }
    if (dc <= thr && dc < dist_max && sc_ > best) { best = sc_; bestid = ic; }
    if (dd <= thr && dd < dist_max && sd  > best) { best = sd;  bestid = id_; }

    float2* out2 = (float2*)out;
    if (best > a45.x) {
        const float4 pr = pos[bestid];
        const float code = __ldg(code_p);
        out2[g * 3 + 0] = make_float2(pr.x, pr.y);
        out2[g * 3 + 1] = make_float2(pr.z, pr.w);
        out2[g * 3 + 2] = make_float2(best, code);
    } else {
        out2[g * 3 + 0] = a01;
        out2[g * 3 + 1] = a23;
        out2[g * 3 + 2] = a45;
    }
}

// ---------------------------------------------------------------------------
// Inputs (metadata order): pos (4096,4) f32, scores (4096,) f32,
// grid (65536,2) f32, accu (65536,6) f32, scale () f32, code () f32.
// ---------------------------------------------------------------------------
extern "C" void kernel_launch(void* const* d_in, const int* in_sizes, int n_in,
                              void* d_out, int out_size)
{
    const float4* pos    = (const float4*)d_in[0];
    const float*  scores = (const float*) d_in[1];
    const float2* grid   = (const float2*)d_in[2];
    const float*  accu   = (const float*) d_in[3];
    const float*  scale  = (const float*) d_in[4];
    const float*  code   = (const float*) d_in[5];
    float* out = (float*)d_out;

    pump_fused_kernel<<<NBLK, BLOCK_T>>>(pos, scores, grid, accu,
                                         scale, code, out);
}

// round 7
// speedup vs baseline: 1.4090x; 1.0030x over previous
#include <cuda_runtime.h>
#include <cfloat>
#include <climits>
#include <math.h>

#define NPTS     4096
#define G_TOTAL  65536
#define NBUCK    64
#define INV_CELL (1.0f / 16.0f)
#define NEG_INF_F (__int_as_float(0xff800000))

#define BLOCK_T  512    // threads per block
#define GPTS     256    // grid points per block (one grid row)
#define NBLK     (G_TOTAL / GPTS)   // 256 blocks; 2 CTA/SM -> all resident
#define CAPB     16     // per-bucket capacity
#define OCAP     64     // overflow list capacity
#define PAD      0.25f  // window padding covering reference d2 rounding slack

// Monotonic float<->int key mapping (handles negatives)
__device__ __forceinline__ int f2ord(float f) {
    int i = __float_as_int(f);
    return (i >= 0) ? i : (i ^ 0x7fffffff);
}
__device__ __forceinline__ float ord2f(int i) {
    return __int_as_float((i >= 0) ? i : (i ^ 0x7fffffff));
}

// Lexicographic (d, pid) top-4 insertion — exactly matches top_k tie-breaking.
__device__ __forceinline__ void insert4(
    float d, int pid, float sc,
    float& da, float& db, float& dc, float& dd,
    int& ia, int& ib, int& ic, int& id_,
    float& sa, float& sb, float& sc_, float& sd)
{
    if (d < dd || (d == dd && pid < id_)) {
        dd = d; id_ = pid; sd = sc;
        if (dd < dc || (dd == dc && id_ < ic)) {
            float td = dc; int ti = ic; float ts = sc_;
            dc = dd; ic = id_; sc_ = sd;
            dd = td; id_ = ti; sd = ts;
            if (dc < db || (dc == db && ic < ib)) {
                td = db; ti = ib; ts = sb;
                db = dc; ib = ic; sb = sc_;
                dc = td; ic = ti; sc_ = ts;
                if (db < da || (db == da && ib < ia)) {
                    td = da; ti = ia; ts = sa;
                    da = db; ia = ib; sa = sb;
                    db = td; ib = ti; sb = ts;
                }
            }
        }
    }
}

// ---------------------------------------------------------------------------
// Single fused kernel, all blocks resident: 256 blocks x 512 threads
// (2 CTAs/SM -> two independent latency chains per SM).
// Phase A: all 512 threads scan the 4096 points (8 coalesced float4 loads)
//          and bin the block's y-strip survivors into smem x-buckets.
// Phase B: threads 0..255 each finish one grid point.
// All gmem inputs are loaded up front (max MLP before the first barrier).
// ---------------------------------------------------------------------------
__global__ __launch_bounds__(BLOCK_T) void pump_fused_kernel(
    const float4* __restrict__ pos,      // (NPTS, 4)
    const float*  __restrict__ scores,   // (NPTS,)
    const float2* __restrict__ grid,     // (G, 2)
    const float*  __restrict__ accu,     // (G, 6)
    const float*  __restrict__ scale_p,
    const float*  __restrict__ code_p,
    float*        __restrict__ out)      // (G, 6)
{
    __shared__ float4 s_buck[NBUCK * CAPB];
    __shared__ int    s_bpid[NBUCK * CAPB];
    __shared__ int    s_cnt[NBUCK];
    __shared__ float4 s_ovf[OCAP];
    __shared__ int    s_opid[OCAP];
    __shared__ int    s_ocnt, s_fb, s_ymin, s_ymax;

    const int tid = threadIdx.x;
    const int lane = tid & 31;
    const bool is_g = (tid < GPTS);
    const int g = blockIdx.x * GPTS + (is_g ? tid : 0);

    // ---- issue ALL independent gmem loads up front (one MLP batch) ----
    const float scale = __ldg(scale_p);
    const float code  = __ldg(code_p);

    float gx = 0.0f, gy = 0.0f;
    float2 a01, a23, a45;
    const float2* acc2 = (const float2*)accu;
    if (is_g) {
        const float2 gp = grid[g];
        gx = gp.x; gy = gp.y;
        a01 = acc2[g * 3 + 0];
        a23 = acc2[g * 3 + 1];
        a45 = acc2[g * 3 + 2];
    }
    const float g2 = __fadd_rn(__fmul_rn(gx, gx), __fmul_rn(gy, gy));

    const float dist_max = __fsub_rn(__fmul_rn(8.0f, scale), 1e-7f);
    const float r = dist_max;
    const float rp = r + PAD;   // padded window radius

    // ---- init smem ----
    if (tid < NBUCK) s_cnt[tid] = 0;
    if (tid == 0) { s_ocnt = 0; s_fb = 0; s_ymin = INT_MAX; s_ymax = INT_MIN; }
    __syncthreads();

    // ---- block y-range (warp reduce, lane-0 atomics) ----
    if (is_g) {
        int lo = f2ord(gy), hi = lo;
        #pragma unroll
        for (int o = 16; o > 0; o >>= 1) {
            lo = min(lo, __shfl_xor_sync(0xffffffffu, lo, o));
            hi = max(hi, __shfl_xor_sync(0xffffffffu, hi, o));
        }
        if (lane == 0) { atomicMin(&s_ymin, lo); atomicMax(&s_ymax, hi); }
    }
    __syncthreads();
    const float ylo = ord2f(s_ymin) - rp;
    const float yhi = ord2f(s_ymax) + rp;

    // ---- Phase A: scan all points, bin survivors into x-buckets ----
    #pragma unroll
    for (int i = 0; i < NPTS / BLOCK_T; i++) {
        const int idx = tid + i * BLOCK_T;
        const float4 p = pos[idx];
        if (p.y > ylo && p.y < yhi) {
            int bx = (int)floorf(p.x * INV_CELL);
            bx = min(NBUCK - 1, max(0, bx));
            const int slot = atomicAdd(&s_cnt[bx], 1);
            const float p2 = __fadd_rn(__fmul_rn(p.x, p.x), __fmul_rn(p.y, p.y));
            const float sc = scores[idx];
            const float4 e = make_float4(p.x, p.y, p2, sc);
            if (slot < CAPB) {
                s_buck[bx * CAPB + slot] = e;
                s_bpid[bx * CAPB + slot] = idx;
            } else {
                const int o = atomicAdd(&s_ocnt, 1);
                if (o < OCAP) { s_ovf[o] = e; s_opid[o] = idx; }
                else s_fb = 1;   // pathological input: full-scan fallback
            }
        }
    }
    __syncthreads();

    if (!is_g) return;

    // ---- Phase B: top-4 by (d, pid) over the padded x-window ----
    float da = FLT_MAX, db = FLT_MAX, dc = FLT_MAX, dd = FLT_MAX;
    int   ia = INT_MAX, ib = INT_MAX, ic = INT_MAX, id_ = INT_MAX;
    float sa = 0.0f,    sb = 0.0f,    sc_ = 0.0f,   sd = 0.0f;

    if (!s_fb) {
        int bx0 = (int)floorf((gx - rp) * INV_CELL);
        int bx1 = (int)floorf((gx + rp) * INV_CELL);
        bx0 = min(NBUCK - 1, max(0, bx0));
        bx1 = min(NBUCK - 1, max(0, bx1));

        for (int bx = bx0; bx <= bx1; bx++) {
            const int n = min(s_cnt[bx], CAPB);
            const int base = bx * CAPB;
            for (int k = 0; k < n; k++) {
                const float4 e = s_buck[base + k];
                const int pid = s_bpid[base + k];
                const float dot = __fmaf_rn(e.y, gy, __fmul_rn(e.x, gx));
                const float d2 = __fsub_rn(__fadd_rn(e.z, g2),
                                           __fmul_rn(2.0f, dot));
                const float d = sqrtf(fmaxf(d2, 1e-12f));
                insert4(d, pid, e.w, da, db, dc, dd, ia, ib, ic, id_,
                        sa, sb, sc_, sd);
            }
        }
        const int on = min(s_ocnt, OCAP);
        for (int k = 0; k < on; k++) {
            const float4 e = s_ovf[k];
            const int pid = s_opid[k];
            const float dot = __fmaf_rn(e.y, gy, __fmul_rn(e.x, gx));
            const float d2 = __fsub_rn(__fadd_rn(e.z, g2),
                                       __fmul_rn(2.0f, dot));
            const float d = sqrtf(fmaxf(d2, 1e-12f));
            insert4(d, pid, e.w, da, db, dc, dd, ia, ib, ic, id_,
                    sa, sb, sc_, sd);
        }
    } else {
        // Fallback: scan everything from gmem (correct for any input).
        for (int idx = 0; idx < NPTS; idx++) {
            const float4 p = pos[idx];
            const float p2 = __fadd_rn(__fmul_rn(p.x, p.x), __fmul_rn(p.y, p.y));
            const float scv = scores[idx];
            const float dot = __fmaf_rn(p.y, gy, __fmul_rn(p.x, gx));
            const float d2 = __fsub_rn(__fadd_rn(p2, g2),
                                       __fmul_rn(2.0f, dot));
            const float d = sqrtf(fmaxf(d2, 1e-12f));
            insert4(d, idx, scv, da, db, dc, dd, ia, ib, ic, id_,
                    sa, sb, sc_, sd);
        }
    }

    // ---- Finalize: filter (d <= 2*d0) & (d < dist_max); max score,
    //      first occurrence wins ties (strict >) ----
    const float thr = __fmul_rn(2.0f, da);   // exact (power of 2)

    float best = NEG_INF_F;
    int bestid = 0;
    if (da <= thr && da < dist_max && sa  > best) { best = sa;  bestid = ia; }
    if (db <= thr && db < dist_max && sb  > best) { best = sb;  bestid = ib; }
    if (dc <= thr && dc < dist_max && sc_ > best) { best = sc_; bestid = ic; }
    if (dd <= thr && dd < dist_max && sd  > best) { best = sd;  bestid = id_; }

    float2* out2 = (float2*)out;
    if (best > a45.x) {
        const float4 pr = pos[bestid];
        out2[g * 3 + 0] = make_float2(pr.x, pr.y);
        out2[g * 3 + 1] = make_float2(pr.z, pr.w);
        out2[g * 3 + 2] = make_float2(best, code);
    } else {
        out2[g * 3 + 0] = a01;
        out2[g * 3 + 1] = a23;
        out2[g * 3 + 2] = a45;
    }
}

// ---------------------------------------------------------------------------
// Inputs (metadata order): pos (4096,4) f32, scores (4096,) f32,
// grid (65536,2) f32, accu (65536,6) f32, scale () f32, code () f32.
// ---------------------------------------------------------------------------
extern "C" void kernel_launch(void* const* d_in, const int* in_sizes, int n_in,
                              void* d_out, int out_size)
{
    const float4* pos    = (const float4*)d_in[0];
    const float*  scores = (const float*) d_in[1];
    const float2* grid   = (const float2*)d_in[2];
    const float*  accu   = (const float*) d_in[3];
    const float*  scale  = (const float*) d_in[4];
    const float*  code   = (const float*) d_in[5];
    float* out = (float*)d_out;

    pump_fused_kernel<<<NBLK, BLOCK_T>>>(pos, scores, grid, accu,
                                         scale, code, out);
}